// round 1
// baseline (speedup 1.0000x reference)
#include <cuda_runtime.h>

#define NN 20000
#define EE 160000
#define E2 320000
#define HH 128

// Scratch (static device globals -- no allocation at runtime)
__device__ float g_h[NN * HH];     // running node features (first N*F valid)
__device__ float g_adst[NN * HH];  // h @ w1[0:F]   (target-side projection)
__device__ float g_asrc[NN * HH];  // h @ w1[F:2F]  (source-side projection)
__device__ float g_acc[NN * HH];   // edge aggregation accumulator
__device__ float g_t1[NN * HH];    // TAG propagation ping
__device__ float g_t2[NN * HH];    // TAG propagation pong
__device__ float g_out[NN * HH];   // TAG output accumulator
__device__ float g_deg[NN];
__device__ float g_dis[NN];

__global__ void k_zero(float* p, int n) {
    int i = blockIdx.x * blockDim.x + threadIdx.x;
    if (i < n) p[i] = 0.f;
}

__global__ void k_deg(const int* __restrict__ ei) {
    int e = blockIdx.x * blockDim.x + threadIdx.x;
    if (e < EE) {
        atomicAdd(&g_deg[ei[e]], 1.f);       // dst0 side
        atomicAdd(&g_deg[ei[e + EE]], 1.f);  // reversed copy: src0 becomes dst
    }
}

__global__ void k_dis() {
    int v = blockIdx.x * blockDim.x + threadIdx.x;
    if (v < NN) {
        float d = g_deg[v];
        g_dis[v] = d > 0.f ? rsqrtf(d) : 0.f;
    }
}

// h16[v] = relu(mask[v]@w1 + b1)@w2 + b2 + x[v]   (thread per node)
__global__ void k_maskmlp(const float* __restrict__ x, const float* __restrict__ mask,
                          const float* __restrict__ w1, const float* __restrict__ b1,
                          const float* __restrict__ w2, const float* __restrict__ b2,
                          float* __restrict__ hout) {
    int v = blockIdx.x * blockDim.x + threadIdx.x;
    if (v >= NN) return;
    float m[16], out[16];
#pragma unroll
    for (int i = 0; i < 16; i++) m[i] = mask[v * 16 + i];
#pragma unroll
    for (int o = 0; o < 16; o++) out[o] = b2[o];
    for (int j = 0; j < HH; j++) {
        float a = b1[j];
#pragma unroll
        for (int i = 0; i < 16; i++) a = fmaf(m[i], w1[i * HH + j], a);
        a = fmaxf(a, 0.f);
#pragma unroll
        for (int o = 0; o < 16; o++) out[o] = fmaf(a, w2[j * 16 + o], out[o]);
    }
#pragma unroll
    for (int o = 0; o < 16; o++) hout[v * 16 + o] = out[o] + x[v * 16 + o];
}

// a_dst = h @ w1[0:F], a_src = h @ w1[F:2F]; also zeroes g_acc. Thread per (v,j).
__global__ void k_ea_pre(const float* __restrict__ hin, const float* __restrict__ w1, int F) {
    int t = blockIdx.x * blockDim.x + threadIdx.x;
    if (t >= NN * HH) return;
    int v = t >> 7, j = t & 127;
    const float* hr = hin + v * F;
    float ad = 0.f, as = 0.f;
    for (int i = 0; i < F; i++) {
        float hv = hr[i];
        ad = fmaf(hv, w1[i * HH + j], ad);
        as = fmaf(hv, w1[(F + i) * HH + j], as);
    }
    g_adst[t] = ad;
    g_asrc[t] = as;
    g_acc[t] = 0.f;
}

// warp per edge: z = a_dst[d] + a_src[s] + ea@w1ea + b1; acc[d] += relu(z)
__global__ void k_ea_edge(const int* __restrict__ ei, const float* __restrict__ eattr,
                          const float* __restrict__ w1ea, const float* __restrict__ b1) {
    __shared__ float sw[16 * HH];
    __shared__ float sb[HH];
    for (int i = threadIdx.x; i < 16 * HH; i += blockDim.x) sw[i] = w1ea[i];
    for (int i = threadIdx.x; i < HH; i += blockDim.x) sb[i] = b1[i];
    __syncthreads();
    int gw = blockIdx.x * (blockDim.x >> 5) + (threadIdx.x >> 5);
    int lane = threadIdx.x & 31;
    if (gw >= E2) return;
    int e = gw;
    int s = ei[e];                               // src[e] = ei[e] for both halves
    int d = (e < EE) ? ei[e + EE] : ei[e - EE];  // dst
    int er = (e < EE) ? e : e - EE;              // edge_attr row
    float eav = (lane < 16) ? __ldg(&eattr[er * 16 + lane]) : 0.f;
    float z[4];
#pragma unroll
    for (int k = 0; k < 4; k++) {
        int j = lane + 32 * k;
        z[k] = g_adst[d * HH + j] + g_asrc[s * HH + j] + sb[j];
    }
#pragma unroll
    for (int i = 0; i < 16; i++) {
        float a = __shfl_sync(0xffffffffu, eav, i);
#pragma unroll
        for (int k = 0; k < 4; k++) z[k] = fmaf(a, sw[i * HH + lane + 32 * k], z[k]);
    }
#pragma unroll
    for (int k = 0; k < 4; k++) {
        float r = fmaxf(z[k], 0.f);
        atomicAdd(&g_acc[d * HH + lane + 32 * k], r);
    }
}

// out[v] = maybe_relu( acc[v]@w2 + deg[v]*b2 ).  Thread per (v,o).
__global__ void k_ea_post(const float* __restrict__ w2, const float* __restrict__ b2,
                          float* __restrict__ out, int O, int do_relu) {
    int t = blockIdx.x * blockDim.x + threadIdx.x;
    if (t >= NN * O) return;
    int v = t / O, o = t - v * O;
    float acc = g_deg[v] * b2[o];
    const float* ar = g_acc + v * HH;
    for (int j = 0; j < HH; j++) acc = fmaf(ar[j], w2[j * O + o], acc);
    out[t] = do_relu ? fmaxf(acc, 0.f) : acc;
}

// TAG matmul accumulate. mode 0: g_out = t@lin. mode 1: g_out += t@lin.
// mode 2: hout = relu(g_out + t@lin + b)
__global__ void k_tagmm(const float* __restrict__ t, const float* __restrict__ lin,
                        const float* __restrict__ b, float* __restrict__ hout, int mode) {
    int id = blockIdx.x * blockDim.x + threadIdx.x;
    if (id >= NN * HH) return;
    int v = id >> 7, o = id & 127;
    float acc = (mode == 0) ? 0.f : g_out[id];
    const float* tr = t + v * HH;
    for (int j = 0; j < HH; j++) acc = fmaf(tr[j], lin[j * HH + o], acc);
    if (mode == 2) hout[id] = fmaxf(acc + b[o], 0.f);
    else g_out[id] = acc;
}

// warp per edge: tout[d] += dis[s]*dis[d] * tin[s]
__global__ void k_prop(const int* __restrict__ ei, const float* __restrict__ tin,
                       float* __restrict__ tout) {
    int gw = blockIdx.x * (blockDim.x >> 5) + (threadIdx.x >> 5);
    int lane = threadIdx.x & 31;
    if (gw >= E2) return;
    int e = gw;
    int s = ei[e];
    int d = (e < EE) ? ei[e + EE] : ei[e - EE];
    float nrm = g_dis[s] * g_dis[d];
#pragma unroll
    for (int k = 0; k < 4; k++) {
        int j = lane + 32 * k;
        atomicAdd(&tout[d * HH + j], nrm * tin[s * HH + j]);
    }
}

extern "C" void kernel_launch(void* const* d_in, const int* in_sizes, int n_in,
                              void* d_out, int out_size) {
    // Input order: dict order (edge_index at 3) or reference-signature order
    // (edge_index last). Disambiguate by in_sizes[3] (320000 vs 2048).
    int eidx, wb;
    if (in_sizes[3] == 2 * EE) { eidx = 3; wb = 4; }
    else                       { eidx = n_in - 1; wb = 3; }

    const float* x     = (const float*)d_in[0];
    const float* mask  = (const float*)d_in[1];
    const float* eattr = (const float*)d_in[2];
    const int*   ei    = (const int*)d_in[eidx];
    const float* m_w1   = (const float*)d_in[wb + 0];
    const float* m_b1   = (const float*)d_in[wb + 1];
    const float* m_w2   = (const float*)d_in[wb + 2];
    const float* m_b2   = (const float*)d_in[wb + 3];
    const float* ea0_w1 = (const float*)d_in[wb + 4];
    const float* ea0_b1 = (const float*)d_in[wb + 5];
    const float* ea0_w2 = (const float*)d_in[wb + 6];
    const float* ea0_b2 = (const float*)d_in[wb + 7];
    const float* tag0_w = (const float*)d_in[wb + 8];
    const float* tag0_b = (const float*)d_in[wb + 9];
    const float* ea1_w1 = (const float*)d_in[wb + 10];
    const float* ea1_b1 = (const float*)d_in[wb + 11];
    const float* ea1_w2 = (const float*)d_in[wb + 12];
    const float* ea1_b2 = (const float*)d_in[wb + 13];
    const float* tag1_w = (const float*)d_in[wb + 14];
    const float* tag1_b = (const float*)d_in[wb + 15];
    const float* ea2_w1 = (const float*)d_in[wb + 16];
    const float* ea2_b1 = (const float*)d_in[wb + 17];
    const float* ea2_w2 = (const float*)d_in[wb + 18];
    const float* ea2_b2 = (const float*)d_in[wb + 19];

    float *p_h, *p_t1, *p_t2, *p_deg;
    cudaGetSymbolAddress((void**)&p_h, g_h);
    cudaGetSymbolAddress((void**)&p_t1, g_t1);
    cudaGetSymbolAddress((void**)&p_t2, g_t2);
    cudaGetSymbolAddress((void**)&p_deg, g_deg);

    const int TB = 256;
    const int gN    = (NN + TB - 1) / TB;
    const int gNH   = (NN * HH + TB - 1) / TB;
    const int gE    = (EE + TB - 1) / TB;
    const int gEdge = (E2 + (TB / 32) - 1) / (TB / 32);  // warp per edge

    // degrees + norms
    k_zero<<<gN, TB>>>(p_deg, NN);
    k_deg<<<gE, TB>>>(ei);
    k_dis<<<gN, TB>>>();

    // mask MLP + residual -> g_h [N,16]
    k_maskmlp<<<gN, TB>>>(x, mask, m_w1, m_b1, m_w2, m_b2, p_h);

    // EA0 (F=16) -> g_h [N,128], relu
    k_ea_pre<<<gNH, TB>>>(p_h, ea0_w1, 16);
    k_ea_edge<<<gEdge, TB>>>(ei, eattr, ea0_w1 + 2 * 16 * HH, ea0_b1);
    k_ea_post<<<gNH, TB>>>(ea0_w2, ea0_b2, p_h, HH, 1);

    // TAG0
    k_tagmm<<<gNH, TB>>>(p_h, tag0_w + 0 * HH * HH, nullptr, nullptr, 0);
    k_zero<<<gNH, TB>>>(p_t1, NN * HH);
    k_prop<<<gEdge, TB>>>(ei, p_h, p_t1);
    k_tagmm<<<gNH, TB>>>(p_t1, tag0_w + 1 * HH * HH, nullptr, nullptr, 1);
    k_zero<<<gNH, TB>>>(p_t2, NN * HH);
    k_prop<<<gEdge, TB>>>(ei, p_t1, p_t2);
    k_tagmm<<<gNH, TB>>>(p_t2, tag0_w + 2 * HH * HH, nullptr, nullptr, 1);
    k_zero<<<gNH, TB>>>(p_t1, NN * HH);
    k_prop<<<gEdge, TB>>>(ei, p_t2, p_t1);
    k_tagmm<<<gNH, TB>>>(p_t1, tag0_w + 3 * HH * HH, tag0_b, p_h, 2);

    // EA1 (F=128) -> g_h [N,128], relu
    k_ea_pre<<<gNH, TB>>>(p_h, ea1_w1, HH);
    k_ea_edge<<<gEdge, TB>>>(ei, eattr, ea1_w1 + 2 * HH * HH, ea1_b1);
    k_ea_post<<<gNH, TB>>>(ea1_w2, ea1_b2, p_h, HH, 1);

    // TAG1
    k_tagmm<<<gNH, TB>>>(p_h, tag1_w + 0 * HH * HH, nullptr, nullptr, 0);
    k_zero<<<gNH, TB>>>(p_t1, NN * HH);
    k_prop<<<gEdge, TB>>>(ei, p_h, p_t1);
    k_tagmm<<<gNH, TB>>>(p_t1, tag1_w + 1 * HH * HH, nullptr, nullptr, 1);
    k_zero<<<gNH, TB>>>(p_t2, NN * HH);
    k_prop<<<gEdge, TB>>>(ei, p_t1, p_t2);
    k_tagmm<<<gNH, TB>>>(p_t2, tag1_w + 2 * HH * HH, nullptr, nullptr, 1);
    k_zero<<<gNH, TB>>>(p_t1, NN * HH);
    k_prop<<<gEdge, TB>>>(ei, p_t2, p_t1);
    k_tagmm<<<gNH, TB>>>(p_t1, tag1_w + 3 * HH * HH, tag1_b, p_h, 2);

    // EA2 (F=128, OUT=16, no relu) -> d_out
    k_ea_pre<<<gNH, TB>>>(p_h, ea2_w1, HH);
    k_ea_edge<<<gEdge, TB>>>(ei, eattr, ea2_w1 + 2 * HH * HH, ea2_b1);
    const int gNO = (NN * 16 + TB - 1) / TB;
    k_ea_post<<<gNO, TB>>>(ea2_w2, ea2_b2, (float*)d_out, 16, 0);
}

// round 2
// speedup vs baseline: 1.8784x; 1.8784x over previous
#include <cuda_runtime.h>

#define NN 20000
#define EE 160000
#define E2 320000
#define HH 128

#define MM_ACC 1
#define MM_RELU 2
#define MM_BIAS 4
#define MM_BIASDEG 8

// ---------------- scratch (static device globals) ----------------
__device__ float g_h[NN * HH];     // running node features
__device__ float g_adst[NN * HH];  // h @ w1_dst
__device__ float g_asrc[NN * HH];  // h @ w1_src
__device__ float g_acc[NN * HH];   // edge-agg accumulator (pre-w2)
__device__ float g_t1[NN * HH];
__device__ float g_t2[NN * HH];
__device__ float g_out[NN * HH];   // TAG accumulator
__device__ float g_dis[NN];
__device__ float g_degf[NN];
__device__ int g_rowptr[NN + 1];
__device__ int g_cursor[NN];
__device__ int g_csr_src[E2];
__device__ int g_csr_ea[E2];

// ---------------- CSR build ----------------
__global__ void k_zero_int(int* p, int n) {
    int i = blockIdx.x * blockDim.x + threadIdx.x;
    if (i < n) p[i] = 0;
}

__global__ void k_count(const int* __restrict__ ei) {
    int e = blockIdx.x * blockDim.x + threadIdx.x;
    if (e >= E2) return;
    int d = (e < EE) ? ei[e + EE] : ei[e - EE];
    atomicAdd(&g_cursor[d], 1);
}

// single-block exclusive scan of g_cursor -> g_rowptr; resets g_cursor to 0
__global__ void k_scan() {
    __shared__ int s[1024];
    int tid = threadIdx.x;
    int carry = 0;
    for (int base = 0; base < NN; base += 1024) {
        int i = base + tid;
        int v = (i < NN) ? g_cursor[i] : 0;
        if (i < NN) g_cursor[i] = 0;
        s[tid] = v;
        __syncthreads();
        for (int off = 1; off < 1024; off <<= 1) {
            int t = (tid >= off) ? s[tid - off] : 0;
            __syncthreads();
            s[tid] += t;
            __syncthreads();
        }
        if (i < NN) g_rowptr[i] = carry + s[tid] - v;
        carry += s[1023];
        __syncthreads();
    }
    if (tid == 0) g_rowptr[NN] = carry;
}

__global__ void k_fill(const int* __restrict__ ei) {
    int e = blockIdx.x * blockDim.x + threadIdx.x;
    if (e >= E2) return;
    int srow, d, er;
    if (e < EE) { srow = ei[e]; d = ei[e + EE]; er = e; }
    else        { srow = ei[e]; d = ei[e - EE]; er = e - EE; }
    int idx = g_rowptr[d] + atomicAdd(&g_cursor[d], 1);
    g_csr_src[idx] = srow;
    g_csr_ea[idx] = er;
}

__global__ void k_dis() {
    int v = blockIdx.x * blockDim.x + threadIdx.x;
    if (v >= NN) return;
    int deg = g_rowptr[v + 1] - g_rowptr[v];
    float df = (float)deg;
    g_degf[v] = df;
    g_dis[v] = deg > 0 ? rsqrtf(df) : 0.f;
}

// ---------------- mask MLP + residual ----------------
__global__ void k_maskmlp(const float* __restrict__ x, const float* __restrict__ mask,
                          const float* __restrict__ w1, const float* __restrict__ b1,
                          const float* __restrict__ w2, const float* __restrict__ b2,
                          float* __restrict__ hout) {
    __shared__ float sw1[16 * HH], sb1[HH], sw2[HH * 16], sb2[16];
    for (int i = threadIdx.x; i < 16 * HH; i += blockDim.x) { sw1[i] = w1[i]; sw2[i] = w2[i]; }
    for (int i = threadIdx.x; i < HH; i += blockDim.x) sb1[i] = b1[i];
    if (threadIdx.x < 16) sb2[threadIdx.x] = b2[threadIdx.x];
    __syncthreads();
    int v = blockIdx.x * blockDim.x + threadIdx.x;
    if (v >= NN) return;
    float m[16], out[16];
#pragma unroll
    for (int i = 0; i < 16; i++) m[i] = mask[v * 16 + i];
#pragma unroll
    for (int o = 0; o < 16; o++) out[o] = sb2[o];
#pragma unroll 4
    for (int j = 0; j < HH; j++) {
        float a = sb1[j];
#pragma unroll
        for (int i = 0; i < 16; i++) a = fmaf(m[i], sw1[i * HH + j], a);
        a = fmaxf(a, 0.f);
#pragma unroll
        for (int o = 0; o < 16; o++) out[o] = fmaf(a, sw2[j * 16 + o], out[o]);
    }
#pragma unroll
    for (int o = 0; o < 16; o++) hout[v * 16 + o] = out[o] + x[v * 16 + o];
}

// ---------------- tiled matmul: Cout[N,128] = op( A[N,F] @ W[F,128] ) ----------------
// block = 256 threads, tile = 32 nodes x 128 outputs, 4x4 register blocking
__global__ void k_mm(const float* __restrict__ A, const float* __restrict__ W,
                     const float* __restrict__ Cin, float* __restrict__ Cout,
                     int F, int flags, const float* __restrict__ bias) {
    extern __shared__ float sm[];
    float* sw = sm;             // F*128
    float* sh = sm + F * HH;    // 32*F
    int tid = threadIdx.x;
    for (int i = tid * 4; i < F * HH; i += blockDim.x * 4)
        *(float4*)&sw[i] = *(const float4*)&W[i];
    int vbase = blockIdx.x * 32;
    for (int i = tid * 4; i < 32 * F; i += blockDim.x * 4)
        *(float4*)&sh[i] = *(const float4*)&A[vbase * F + i];
    __syncthreads();

    int w = tid >> 5, lane = tid & 31;
    float acc[4][4];
#pragma unroll
    for (int i = 0; i < 4; i++)
#pragma unroll
        for (int k = 0; k < 4; k++) acc[i][k] = 0.f;

    const float* h0 = &sh[(w * 4 + 0) * F];
    const float* h1 = &sh[(w * 4 + 1) * F];
    const float* h2 = &sh[(w * 4 + 2) * F];
    const float* h3 = &sh[(w * 4 + 3) * F];
#pragma unroll 4
    for (int j = 0; j < F; j++) {
        float4 wv = *(float4*)&sw[j * HH + lane * 4];
        float hv0 = h0[j], hv1 = h1[j], hv2 = h2[j], hv3 = h3[j];
        acc[0][0] = fmaf(hv0, wv.x, acc[0][0]); acc[0][1] = fmaf(hv0, wv.y, acc[0][1]);
        acc[0][2] = fmaf(hv0, wv.z, acc[0][2]); acc[0][3] = fmaf(hv0, wv.w, acc[0][3]);
        acc[1][0] = fmaf(hv1, wv.x, acc[1][0]); acc[1][1] = fmaf(hv1, wv.y, acc[1][1]);
        acc[1][2] = fmaf(hv1, wv.z, acc[1][2]); acc[1][3] = fmaf(hv1, wv.w, acc[1][3]);
        acc[2][0] = fmaf(hv2, wv.x, acc[2][0]); acc[2][1] = fmaf(hv2, wv.y, acc[2][1]);
        acc[2][2] = fmaf(hv2, wv.z, acc[2][2]); acc[2][3] = fmaf(hv2, wv.w, acc[2][3]);
        acc[3][0] = fmaf(hv3, wv.x, acc[3][0]); acc[3][1] = fmaf(hv3, wv.y, acc[3][1]);
        acc[3][2] = fmaf(hv3, wv.z, acc[3][2]); acc[3][3] = fmaf(hv3, wv.w, acc[3][3]);
    }

    int o = lane * 4;
#pragma unroll
    for (int i = 0; i < 4; i++) {
        int v = vbase + w * 4 + i;
        float4 r = make_float4(acc[i][0], acc[i][1], acc[i][2], acc[i][3]);
        if (flags & MM_BIAS) {
            r.x += bias[o]; r.y += bias[o + 1]; r.z += bias[o + 2]; r.w += bias[o + 3];
        }
        if (flags & MM_BIASDEG) {
            float dg = g_degf[v];
            r.x += dg * bias[o]; r.y += dg * bias[o + 1];
            r.z += dg * bias[o + 2]; r.w += dg * bias[o + 3];
        }
        if (flags & MM_ACC) {
            float4 c = *(const float4*)&Cin[v * HH + o];
            r.x += c.x; r.y += c.y; r.z += c.z; r.w += c.w;
        }
        if (flags & MM_RELU) {
            r.x = fmaxf(r.x, 0.f); r.y = fmaxf(r.y, 0.f);
            r.z = fmaxf(r.z, 0.f); r.w = fmaxf(r.w, 0.f);
        }
        *(float4*)&Cout[v * HH + o] = r;
    }
}

// ---------------- EA edge gather (warp per dst node), no atomics ----------------
// z_e = adst[d] + asrc[s] + eattr[er] @ w1ea + b1 ;  acc = sum relu(z_e)
// Ofin==0: write acc to g_acc. Ofin==16: fused out[d,0:16] = acc@w2 + deg*b2 (no relu)
__global__ void k_ea_gather(const float* __restrict__ eattr,
                            const float* __restrict__ w1ea, const float* __restrict__ b1,
                            const float* __restrict__ w2, const float* __restrict__ b2,
                            float* __restrict__ out, int Ofin) {
    extern __shared__ float sm[];
    float* sw1 = sm;             // 16*128
    float* sb1 = sm + 16 * HH;   // 128
    float* sw2 = sb1 + HH;       // 128*Ofin
    float* sb2 = sw2 + HH * Ofin;
    float* buf = sb2 + Ofin;     // 8*128 (only used when Ofin)
    int tid = threadIdx.x;
    for (int i = tid; i < 16 * HH; i += blockDim.x) sw1[i] = w1ea[i];
    for (int i = tid; i < HH; i += blockDim.x) sb1[i] = b1[i];
    if (Ofin) {
        for (int i = tid; i < HH * Ofin; i += blockDim.x) sw2[i] = w2[i];
        if (tid < Ofin) sb2[tid] = b2[tid];
    }
    __syncthreads();

    int w = tid >> 5, lane = tid & 31;
    for (int d = blockIdx.x * 8 + w; d < NN; d += gridDim.x * 8) {
        int beg = g_rowptr[d], end = g_rowptr[d + 1];
        float zb[4], acc[4];
#pragma unroll
        for (int k = 0; k < 4; k++) {
            zb[k] = g_adst[d * HH + lane + 32 * k] + sb1[lane + 32 * k];
            acc[k] = 0.f;
        }
        for (int idx = beg; idx < end; idx++) {
            int s = g_csr_src[idx];
            int er = g_csr_ea[idx];
            float eav = (lane < 16) ? eattr[er * 16 + lane] : 0.f;
            float z[4];
#pragma unroll
            for (int k = 0; k < 4; k++) z[k] = zb[k] + g_asrc[s * HH + lane + 32 * k];
#pragma unroll
            for (int i = 0; i < 16; i++) {
                float a = __shfl_sync(0xffffffffu, eav, i);
#pragma unroll
                for (int k = 0; k < 4; k++)
                    z[k] = fmaf(a, sw1[i * HH + lane + 32 * k], z[k]);
            }
#pragma unroll
            for (int k = 0; k < 4; k++) acc[k] += fmaxf(z[k], 0.f);
        }
        if (!Ofin) {
#pragma unroll
            for (int k = 0; k < 4; k++) g_acc[d * HH + lane + 32 * k] = acc[k];
        } else {
#pragma unroll
            for (int k = 0; k < 4; k++) buf[w * HH + lane + 32 * k] = acc[k];
            __syncwarp();
            if (lane < 16) {
                float o = g_degf[d] * sb2[lane];
#pragma unroll 4
                for (int j = 0; j < HH; j++)
                    o = fmaf(buf[w * HH + j], sw2[j * 16 + lane], o);
                out[d * 16 + lane] = o;
            }
            __syncwarp();
        }
    }
}

// ---------------- TAG propagation gather: tout[d] = dis[d] * sum dis[s]*tin[s] ----------------
__global__ void k_prop(const float* __restrict__ tin, float* __restrict__ tout) {
    int w = threadIdx.x >> 5, lane = threadIdx.x & 31;
    for (int d = blockIdx.x * 8 + w; d < NN; d += gridDim.x * 8) {
        int beg = g_rowptr[d], end = g_rowptr[d + 1];
        float acc[4] = {0.f, 0.f, 0.f, 0.f};
        for (int idx = beg; idx < end; idx++) {
            int s = g_csr_src[idx];
            float ds = g_dis[s];
#pragma unroll
            for (int k = 0; k < 4; k++)
                acc[k] = fmaf(ds, tin[s * HH + lane + 32 * k], acc[k]);
        }
        float dd = g_dis[d];
#pragma unroll
        for (int k = 0; k < 4; k++) tout[d * HH + lane + 32 * k] = dd * acc[k];
    }
}

// ---------------- host ----------------
extern "C" void kernel_launch(void* const* d_in, const int* in_sizes, int n_in,
                              void* d_out, int out_size) {
    int eidx, wb;
    if (in_sizes[3] == 2 * EE) { eidx = 3; wb = 4; }
    else                       { eidx = n_in - 1; wb = 3; }

    const float* x     = (const float*)d_in[0];
    const float* mask  = (const float*)d_in[1];
    const float* eattr = (const float*)d_in[2];
    const int*   ei    = (const int*)d_in[eidx];
    const float* m_w1   = (const float*)d_in[wb + 0];
    const float* m_b1   = (const float*)d_in[wb + 1];
    const float* m_w2   = (const float*)d_in[wb + 2];
    const float* m_b2   = (const float*)d_in[wb + 3];
    const float* ea0_w1 = (const float*)d_in[wb + 4];
    const float* ea0_b1 = (const float*)d_in[wb + 5];
    const float* ea0_w2 = (const float*)d_in[wb + 6];
    const float* ea0_b2 = (const float*)d_in[wb + 7];
    const float* tag0_w = (const float*)d_in[wb + 8];
    const float* tag0_b = (const float*)d_in[wb + 9];
    const float* ea1_w1 = (const float*)d_in[wb + 10];
    const float* ea1_b1 = (const float*)d_in[wb + 11];
    const float* ea1_w2 = (const float*)d_in[wb + 12];
    const float* ea1_b2 = (const float*)d_in[wb + 13];
    const float* tag1_w = (const float*)d_in[wb + 14];
    const float* tag1_b = (const float*)d_in[wb + 15];
    const float* ea2_w1 = (const float*)d_in[wb + 16];
    const float* ea2_b1 = (const float*)d_in[wb + 17];
    const float* ea2_w2 = (const float*)d_in[wb + 18];
    const float* ea2_b2 = (const float*)d_in[wb + 19];

    float *p_h, *p_adst, *p_asrc, *p_acc, *p_t1, *p_t2, *p_out;
    int* p_cur;
    cudaGetSymbolAddress((void**)&p_h, g_h);
    cudaGetSymbolAddress((void**)&p_adst, g_adst);
    cudaGetSymbolAddress((void**)&p_asrc, g_asrc);
    cudaGetSymbolAddress((void**)&p_acc, g_acc);
    cudaGetSymbolAddress((void**)&p_t1, g_t1);
    cudaGetSymbolAddress((void**)&p_t2, g_t2);
    cudaGetSymbolAddress((void**)&p_out, g_out);
    cudaGetSymbolAddress((void**)&p_cur, g_cursor);

    static bool attr_done = false;
    if (!attr_done) {
        cudaFuncSetAttribute(k_mm, cudaFuncAttributeMaxDynamicSharedMemorySize, 84 * 1024);
        cudaFuncSetAttribute(k_ea_gather, cudaFuncAttributeMaxDynamicSharedMemorySize, 48 * 1024);
        attr_done = true;
    }

    const int TB = 256;
    const int gN = (NN + TB - 1) / TB;
    const int gE = (E2 + TB - 1) / TB;
    const int TILES = NN / 32;           // 625
    const int gW = (NN + 7) / 8 / TB * TB >= NN ? 2500 : 2500;  // warp-per-node blocks
    const size_t smm128 = (size_t)(HH * HH + 32 * HH) * 4;       // 80KB
    const size_t smm16  = (size_t)(16 * HH + 32 * 16) * 4;       // 10KB
    const size_t sga0   = (size_t)(16 * HH + HH) * 4;            // gather, no epi
    const size_t sga16  = (size_t)(16 * HH + HH + HH * 16 + 16 + 8 * HH) * 4;

    // CSR
    k_zero_int<<<gN, TB>>>(p_cur, NN);
    k_count<<<gE, TB>>>(ei);
    k_scan<<<1, 1024>>>();
    k_fill<<<gE, TB>>>(ei);
    k_dis<<<gN, TB>>>();

    // mask MLP + residual -> g_h [N,16]
    k_maskmlp<<<gN, TB>>>(x, mask, m_w1, m_b1, m_w2, m_b2, p_h);

    // ---- EA0 (F=16) ----
    k_mm<<<TILES, TB, smm16>>>(p_h, ea0_w1, nullptr, p_adst, 16, 0, nullptr);
    k_mm<<<TILES, TB, smm16>>>(p_h, ea0_w1 + 16 * HH, nullptr, p_asrc, 16, 0, nullptr);
    k_ea_gather<<<gW, TB, sga0>>>(eattr, ea0_w1 + 2 * 16 * HH, ea0_b1,
                                  nullptr, nullptr, nullptr, 0);
    k_mm<<<TILES, TB, smm128>>>(p_acc, ea0_w2, nullptr, p_h, HH, MM_RELU | MM_BIASDEG, ea0_b2);

    // ---- TAG0 ----
    k_mm<<<TILES, TB, smm128>>>(p_h, tag0_w, nullptr, p_out, HH, 0, nullptr);
    k_prop<<<gW, TB>>>(p_h, p_t1);
    k_mm<<<TILES, TB, smm128>>>(p_t1, tag0_w + 1 * HH * HH, p_out, p_out, HH, MM_ACC, nullptr);
    k_prop<<<gW, TB>>>(p_t1, p_t2);
    k_mm<<<TILES, TB, smm128>>>(p_t2, tag0_w + 2 * HH * HH, p_out, p_out, HH, MM_ACC, nullptr);
    k_prop<<<gW, TB>>>(p_t2, p_t1);
    k_mm<<<TILES, TB, smm128>>>(p_t1, tag0_w + 3 * HH * HH, p_out, p_h, HH,
                                MM_ACC | MM_RELU | MM_BIAS, tag0_b);

    // ---- EA1 (F=128) ----
    k_mm<<<TILES, TB, smm128>>>(p_h, ea1_w1, nullptr, p_adst, HH, 0, nullptr);
    k_mm<<<TILES, TB, smm128>>>(p_h, ea1_w1 + HH * HH, nullptr, p_asrc, HH, 0, nullptr);
    k_ea_gather<<<gW, TB, sga0>>>(eattr, ea1_w1 + 2 * HH * HH, ea1_b1,
                                  nullptr, nullptr, nullptr, 0);
    k_mm<<<TILES, TB, smm128>>>(p_acc, ea1_w2, nullptr, p_h, HH, MM_RELU | MM_BIASDEG, ea1_b2);

    // ---- TAG1 ----
    k_mm<<<TILES, TB, smm128>>>(p_h, tag1_w, nullptr, p_out, HH, 0, nullptr);
    k_prop<<<gW, TB>>>(p_h, p_t1);
    k_mm<<<TILES, TB, smm128>>>(p_t1, tag1_w + 1 * HH * HH, p_out, p_out, HH, MM_ACC, nullptr);
    k_prop<<<gW, TB>>>(p_t1, p_t2);
    k_mm<<<TILES, TB, smm128>>>(p_t2, tag1_w + 2 * HH * HH, p_out, p_out, HH, MM_ACC, nullptr);
    k_prop<<<gW, TB>>>(p_t2, p_t1);
    k_mm<<<TILES, TB, smm128>>>(p_t1, tag1_w + 3 * HH * HH, p_out, p_h, HH,
                                MM_ACC | MM_RELU | MM_BIAS, tag1_b);

    // ---- EA2 (F=128, OUT=16, no relu) -> d_out ----
    k_mm<<<TILES, TB, smm128>>>(p_h, ea2_w1, nullptr, p_adst, HH, 0, nullptr);
    k_mm<<<TILES, TB, smm128>>>(p_h, ea2_w1 + HH * HH, nullptr, p_asrc, HH, 0, nullptr);
    k_ea_gather<<<gW, TB, sga16>>>(eattr, ea2_w1 + 2 * HH * HH, ea2_b1,
                                   ea2_w2, ea2_b2, (float*)d_out, 16);
}

// round 3
// speedup vs baseline: 2.0101x; 1.0702x over previous
#include <cuda_runtime.h>

#define NN 20000
#define EE 160000
#define E2 320000
#define HH 128

#define MM_ACC 1
#define MM_RELU 2
#define MM_BIAS 4
#define MM_BIASDEG 8

typedef unsigned long long ull;

__device__ __forceinline__ ull pk2(float x) {
    ull r; asm("mov.b64 %0,{%1,%1};" : "=l"(r) : "f"(x)); return r;
}
__device__ __forceinline__ ull pkxy(float x, float y) {
    ull r; asm("mov.b64 %0,{%1,%2};" : "=l"(r) : "f"(x), "f"(y)); return r;
}
__device__ __forceinline__ ull fma2(ull a, ull b, ull c) {
    ull d; asm("fma.rn.f32x2 %0,%1,%2,%3;" : "=l"(d) : "l"(a), "l"(b), "l"(c)); return d;
}
__device__ __forceinline__ ull add2(ull a, ull b) {
    ull d; asm("add.rn.f32x2 %0,%1,%2;" : "=l"(d) : "l"(a), "l"(b)); return d;
}
__device__ __forceinline__ void upk(ull v, float& x, float& y) {
    asm("mov.b64 {%0,%1},%2;" : "=f"(x), "=f"(y) : "l"(v));
}

// ---------------- scratch ----------------
__device__ float g_h[NN * HH];
__device__ float g_adst[NN * HH];
__device__ float g_asrc[NN * HH];
__device__ float g_acc[NN * HH];
__device__ float g_t1[NN * HH];
__device__ float g_t2[NN * HH];
__device__ float g_out[NN * HH];
__device__ float g_dis[NN];
__device__ float g_degf[NN];
__device__ int g_rowptr[NN + 1];
__device__ int g_cursor[NN];
__device__ int g_csr_src[E2];
__device__ int g_csr_ea[E2];

// ---------------- CSR build ----------------
__global__ void k_zero_int(int* p, int n) {
    int i = blockIdx.x * blockDim.x + threadIdx.x;
    if (i < n) p[i] = 0;
}

__global__ void k_count(const int* __restrict__ ei) {
    int e = blockIdx.x * blockDim.x + threadIdx.x;
    if (e >= E2) return;
    int d = (e < EE) ? ei[e + EE] : ei[e - EE];
    atomicAdd(&g_cursor[d], 1);
}

__global__ void k_scan() {
    __shared__ int s[1024];
    int tid = threadIdx.x;
    int carry = 0;
    for (int base = 0; base < NN; base += 1024) {
        int i = base + tid;
        int v = (i < NN) ? g_cursor[i] : 0;
        if (i < NN) g_cursor[i] = 0;
        s[tid] = v;
        __syncthreads();
        for (int off = 1; off < 1024; off <<= 1) {
            int t = (tid >= off) ? s[tid - off] : 0;
            __syncthreads();
            s[tid] += t;
            __syncthreads();
        }
        if (i < NN) g_rowptr[i] = carry + s[tid] - v;
        carry += s[1023];
        __syncthreads();
    }
    if (tid == 0) g_rowptr[NN] = carry;
}

__global__ void k_fill(const int* __restrict__ ei) {
    int e = blockIdx.x * blockDim.x + threadIdx.x;
    if (e >= E2) return;
    int srow, d, er;
    if (e < EE) { srow = ei[e]; d = ei[e + EE]; er = e; }
    else        { srow = ei[e]; d = ei[e - EE]; er = e - EE; }
    int idx = g_rowptr[d] + atomicAdd(&g_cursor[d], 1);
    g_csr_src[idx] = srow;
    g_csr_ea[idx] = er;
}

__global__ void k_dis() {
    int v = blockIdx.x * blockDim.x + threadIdx.x;
    if (v >= NN) return;
    int deg = g_rowptr[v + 1] - g_rowptr[v];
    float df = (float)deg;
    g_degf[v] = df;
    g_dis[v] = deg > 0 ? rsqrtf(df) : 0.f;
}

// ---------------- mask MLP + residual ----------------
__global__ void k_maskmlp(const float* __restrict__ x, const float* __restrict__ mask,
                          const float* __restrict__ w1, const float* __restrict__ b1,
                          const float* __restrict__ w2, const float* __restrict__ b2,
                          float* __restrict__ hout) {
    __shared__ float sw1[16 * HH], sb1[HH], sw2[HH * 16], sb2[16];
    for (int i = threadIdx.x; i < 16 * HH; i += blockDim.x) { sw1[i] = w1[i]; sw2[i] = w2[i]; }
    for (int i = threadIdx.x; i < HH; i += blockDim.x) sb1[i] = b1[i];
    if (threadIdx.x < 16) sb2[threadIdx.x] = b2[threadIdx.x];
    __syncthreads();
    int v = blockIdx.x * blockDim.x + threadIdx.x;
    if (v >= NN) return;
    float m[16], out[16];
#pragma unroll
    for (int i = 0; i < 16; i++) m[i] = mask[v * 16 + i];
#pragma unroll
    for (int o = 0; o < 16; o++) out[o] = sb2[o];
#pragma unroll 4
    for (int j = 0; j < HH; j++) {
        float a = sb1[j];
#pragma unroll
        for (int i = 0; i < 16; i++) a = fmaf(m[i], sw1[i * HH + j], a);
        a = fmaxf(a, 0.f);
#pragma unroll
        for (int o = 0; o < 16; o++) out[o] = fmaf(a, sw2[j * 16 + o], out[o]);
    }
#pragma unroll
    for (int o = 0; o < 16; o++) hout[v * 16 + o] = out[o] + x[v * 16 + o];
}

// ---------------- tiled matmul (persistent, f32x2 packed) ----------------
// block = 256 threads; each grid-stride tile = 32 nodes x 128 outputs
__global__ void k_mm(const float* __restrict__ A, const float* __restrict__ W,
                     const float* __restrict__ Cin, float* __restrict__ Cout,
                     int F, int flags, const float* __restrict__ bias, int ntiles) {
    extern __shared__ float sm[];
    float* sw = sm;             // F*128
    float* sh = sm + F * HH;    // 32*F
    int tid = threadIdx.x;
    for (int i = tid * 4; i < F * HH; i += blockDim.x * 4)
        *(float4*)&sw[i] = *(const float4*)&W[i];
    int w = tid >> 5, lane = tid & 31;

    for (int tile = blockIdx.x; tile < ntiles; tile += gridDim.x) {
        int vbase = tile * 32;
        __syncthreads();
        for (int i = tid * 4; i < 32 * F; i += blockDim.x * 4)
            *(float4*)&sh[i] = *(const float4*)&A[vbase * F + i];
        __syncthreads();

        ull acc[4][2];
#pragma unroll
        for (int i = 0; i < 4; i++) { acc[i][0] = pkxy(0.f, 0.f); acc[i][1] = acc[i][0]; }

        const float* h0 = &sh[(w * 4 + 0) * F];
        const float* h1 = &sh[(w * 4 + 1) * F];
        const float* h2 = &sh[(w * 4 + 2) * F];
        const float* h3 = &sh[(w * 4 + 3) * F];
#pragma unroll 4
        for (int j = 0; j < F; j++) {
            ulonglong2 wv = *(const ulonglong2*)&sw[j * HH + lane * 4];
            ull a0 = pk2(h0[j]), a1 = pk2(h1[j]), a2 = pk2(h2[j]), a3 = pk2(h3[j]);
            acc[0][0] = fma2(a0, wv.x, acc[0][0]); acc[0][1] = fma2(a0, wv.y, acc[0][1]);
            acc[1][0] = fma2(a1, wv.x, acc[1][0]); acc[1][1] = fma2(a1, wv.y, acc[1][1]);
            acc[2][0] = fma2(a2, wv.x, acc[2][0]); acc[2][1] = fma2(a2, wv.y, acc[2][1]);
            acc[3][0] = fma2(a3, wv.x, acc[3][0]); acc[3][1] = fma2(a3, wv.y, acc[3][1]);
        }

        int o = lane * 4;
#pragma unroll
        for (int i = 0; i < 4; i++) {
            int v = vbase + w * 4 + i;
            float4 r;
            upk(acc[i][0], r.x, r.y);
            upk(acc[i][1], r.z, r.w);
            if (flags & MM_BIAS) {
                r.x += bias[o]; r.y += bias[o + 1]; r.z += bias[o + 2]; r.w += bias[o + 3];
            }
            if (flags & MM_BIASDEG) {
                float dg = g_degf[v];
                r.x += dg * bias[o]; r.y += dg * bias[o + 1];
                r.z += dg * bias[o + 2]; r.w += dg * bias[o + 3];
            }
            if (flags & MM_ACC) {
                float4 c = *(const float4*)&Cin[v * HH + o];
                r.x += c.x; r.y += c.y; r.z += c.z; r.w += c.w;
            }
            if (flags & MM_RELU) {
                r.x = fmaxf(r.x, 0.f); r.y = fmaxf(r.y, 0.f);
                r.z = fmaxf(r.z, 0.f); r.w = fmaxf(r.w, 0.f);
            }
            *(float4*)&Cout[v * HH + o] = r;
        }
    }
}

// ---------------- EA edge gather (warp per dst node, f32x2 packed) ----------------
// lane handles features j = lane*4 .. lane*4+3 (contiguous -> 128-bit ld/st)
__global__ void k_ea_gather(const float* __restrict__ eattr,
                            const float* __restrict__ w1ea, const float* __restrict__ b1,
                            const float* __restrict__ w2, const float* __restrict__ b2,
                            float* __restrict__ out, int Ofin) {
    extern __shared__ float sm[];
    float* sw1 = sm;             // 16*128
    float* sb1 = sm + 16 * HH;   // 128
    float* sw2 = sb1 + HH;       // 128*Ofin
    float* sb2 = sw2 + HH * Ofin;
    float* buf = sb2 + Ofin;     // 8*128 when Ofin
    int tid = threadIdx.x;
    for (int i = tid; i < 16 * HH; i += blockDim.x) sw1[i] = w1ea[i];
    for (int i = tid; i < HH; i += blockDim.x) sb1[i] = b1[i];
    if (Ofin) {
        for (int i = tid; i < HH * Ofin; i += blockDim.x) sw2[i] = w2[i];
        if (tid < Ofin) sb2[tid] = b2[tid];
    }
    __syncthreads();

    int w = tid >> 5, lane = tid & 31;
    int jo = lane * 4;
    for (int d = blockIdx.x * 8 + w; d < NN; d += gridDim.x * 8) {
        int beg = g_rowptr[d], end = g_rowptr[d + 1];
        float4 ad = *(const float4*)&g_adst[d * HH + jo];
        ull zb0 = pkxy(ad.x + sb1[jo], ad.y + sb1[jo + 1]);
        ull zb1 = pkxy(ad.z + sb1[jo + 2], ad.w + sb1[jo + 3]);
        float a0 = 0.f, a1 = 0.f, a2 = 0.f, a3 = 0.f;
        for (int idx = beg; idx < end; idx++) {
            int s = g_csr_src[idx];
            int er = g_csr_ea[idx];
            float eav = (lane < 16) ? eattr[er * 16 + lane] : 0.f;
            ulonglong2 as = *(const ulonglong2*)&g_asrc[s * HH + jo];
            ull z0 = add2(zb0, as.x);
            ull z1 = add2(zb1, as.y);
#pragma unroll
            for (int i = 0; i < 16; i++) {
                float a = __shfl_sync(0xffffffffu, eav, i);
                ull ap = pk2(a);
                ulonglong2 wv = *(const ulonglong2*)&sw1[i * HH + jo];
                z0 = fma2(ap, wv.x, z0);
                z1 = fma2(ap, wv.y, z1);
            }
            float f0, f1, f2, f3;
            upk(z0, f0, f1);
            upk(z1, f2, f3);
            a0 += fmaxf(f0, 0.f); a1 += fmaxf(f1, 0.f);
            a2 += fmaxf(f2, 0.f); a3 += fmaxf(f3, 0.f);
        }
        if (!Ofin) {
            *(float4*)&g_acc[d * HH + jo] = make_float4(a0, a1, a2, a3);
        } else {
            *(float4*)&buf[w * HH + jo] = make_float4(a0, a1, a2, a3);
            __syncwarp();
            if (lane < 16) {
                float o = g_degf[d] * sb2[lane];
#pragma unroll 4
                for (int j = 0; j < HH; j++)
                    o = fmaf(buf[w * HH + j], sw2[j * 16 + lane], o);
                out[d * 16 + lane] = o;
            }
            __syncwarp();
        }
    }
}

// ---------------- TAG propagation: tout[d] = dis[d] * sum dis[s]*tin[s] ----------------
__global__ void k_prop(const float* __restrict__ tin, float* __restrict__ tout) {
    int w = threadIdx.x >> 5, lane = threadIdx.x & 31;
    int jo = lane * 4;
    for (int d = blockIdx.x * 8 + w; d < NN; d += gridDim.x * 8) {
        int beg = g_rowptr[d], end = g_rowptr[d + 1];
        float a0 = 0.f, a1 = 0.f, a2 = 0.f, a3 = 0.f;
        for (int idx = beg; idx < end; idx++) {
            int s = g_csr_src[idx];
            float ds = g_dis[s];
            float4 t = *(const float4*)&tin[s * HH + jo];
            a0 = fmaf(ds, t.x, a0); a1 = fmaf(ds, t.y, a1);
            a2 = fmaf(ds, t.z, a2); a3 = fmaf(ds, t.w, a3);
        }
        float dd = g_dis[d];
        *(float4*)&tout[d * HH + jo] = make_float4(dd * a0, dd * a1, dd * a2, dd * a3);
    }
}

// ---------------- host ----------------
extern "C" void kernel_launch(void* const* d_in, const int* in_sizes, int n_in,
                              void* d_out, int out_size) {
    int eidx, wb;
    if (in_sizes[3] == 2 * EE) { eidx = 3; wb = 4; }
    else                       { eidx = n_in - 1; wb = 3; }

    const float* x     = (const float*)d_in[0];
    const float* mask  = (const float*)d_in[1];
    const float* eattr = (const float*)d_in[2];
    const int*   ei    = (const int*)d_in[eidx];
    const float* m_w1   = (const float*)d_in[wb + 0];
    const float* m_b1   = (const float*)d_in[wb + 1];
    const float* m_w2   = (const float*)d_in[wb + 2];
    const float* m_b2   = (const float*)d_in[wb + 3];
    const float* ea0_w1 = (const float*)d_in[wb + 4];
    const float* ea0_b1 = (const float*)d_in[wb + 5];
    const float* ea0_w2 = (const float*)d_in[wb + 6];
    const float* ea0_b2 = (const float*)d_in[wb + 7];
    const float* tag0_w = (const float*)d_in[wb + 8];
    const float* tag0_b = (const float*)d_in[wb + 9];
    const float* ea1_w1 = (const float*)d_in[wb + 10];
    const float* ea1_b1 = (const float*)d_in[wb + 11];
    const float* ea1_w2 = (const float*)d_in[wb + 12];
    const float* ea1_b2 = (const float*)d_in[wb + 13];
    const float* tag1_w = (const float*)d_in[wb + 14];
    const float* tag1_b = (const float*)d_in[wb + 15];
    const float* ea2_w1 = (const float*)d_in[wb + 16];
    const float* ea2_b1 = (const float*)d_in[wb + 17];
    const float* ea2_w2 = (const float*)d_in[wb + 18];
    const float* ea2_b2 = (const float*)d_in[wb + 19];

    float *p_h, *p_adst, *p_asrc, *p_acc, *p_t1, *p_t2, *p_out;
    int* p_cur;
    cudaGetSymbolAddress((void**)&p_h, g_h);
    cudaGetSymbolAddress((void**)&p_adst, g_adst);
    cudaGetSymbolAddress((void**)&p_asrc, g_asrc);
    cudaGetSymbolAddress((void**)&p_acc, g_acc);
    cudaGetSymbolAddress((void**)&p_t1, g_t1);
    cudaGetSymbolAddress((void**)&p_t2, g_t2);
    cudaGetSymbolAddress((void**)&p_out, g_out);
    cudaGetSymbolAddress((void**)&p_cur, g_cursor);

    static bool attr_done = false;
    if (!attr_done) {
        cudaFuncSetAttribute(k_mm, cudaFuncAttributeMaxDynamicSharedMemorySize, 84 * 1024);
        cudaFuncSetAttribute(k_ea_gather, cudaFuncAttributeMaxDynamicSharedMemorySize, 48 * 1024);
        attr_done = true;
    }

    const int TB = 256;
    const int gN = (NN + TB - 1) / TB;
    const int gE = (E2 + TB - 1) / TB;
    const int TILES = NN / 32;   // 625
    const int HB = 296;          // persistent blocks for heavy matmuls (2/SM)
    const int gW = 2500;         // warp-per-node (8 warps/block)
    const size_t smm128 = (size_t)(HH * HH + 32 * HH) * 4;
    const size_t smm16  = (size_t)(16 * HH + 32 * 16) * 4;
    const size_t sga0   = (size_t)(16 * HH + HH) * 4;
    const size_t sga16  = (size_t)(16 * HH + HH + HH * 16 + 16 + 8 * HH) * 4;

    // CSR
    k_zero_int<<<gN, TB>>>(p_cur, NN);
    k_count<<<gE, TB>>>(ei);
    k_scan<<<1, 1024>>>();
    k_fill<<<gE, TB>>>(ei);
    k_dis<<<gN, TB>>>();

    // mask MLP + residual -> g_h [N,16]
    k_maskmlp<<<gN, TB>>>(x, mask, m_w1, m_b1, m_w2, m_b2, p_h);

    // ---- EA0 (F=16) ----
    k_mm<<<TILES, TB, smm16>>>(p_h, ea0_w1, nullptr, p_adst, 16, 0, nullptr, TILES);
    k_mm<<<TILES, TB, smm16>>>(p_h, ea0_w1 + 16 * HH, nullptr, p_asrc, 16, 0, nullptr, TILES);
    k_ea_gather<<<gW, TB, sga0>>>(eattr, ea0_w1 + 2 * 16 * HH, ea0_b1,
                                  nullptr, nullptr, nullptr, 0);
    k_mm<<<HB, TB, smm128>>>(p_acc, ea0_w2, nullptr, p_h, HH, MM_RELU | MM_BIASDEG, ea0_b2, TILES);

    // ---- TAG0 ----
    k_mm<<<HB, TB, smm128>>>(p_h, tag0_w, nullptr, p_out, HH, 0, nullptr, TILES);
    k_prop<<<gW, TB>>>(p_h, p_t1);
    k_mm<<<HB, TB, smm128>>>(p_t1, tag0_w + 1 * HH * HH, p_out, p_out, HH, MM_ACC, nullptr, TILES);
    k_prop<<<gW, TB>>>(p_t1, p_t2);
    k_mm<<<HB, TB, smm128>>>(p_t2, tag0_w + 2 * HH * HH, p_out, p_out, HH, MM_ACC, nullptr, TILES);
    k_prop<<<gW, TB>>>(p_t2, p_t1);
    k_mm<<<HB, TB, smm128>>>(p_t1, tag0_w + 3 * HH * HH, p_out, p_h, HH,
                             MM_ACC | MM_RELU | MM_BIAS, tag0_b, TILES);

    // ---- EA1 (F=128) ----
    k_mm<<<HB, TB, smm128>>>(p_h, ea1_w1, nullptr, p_adst, HH, 0, nullptr, TILES);
    k_mm<<<HB, TB, smm128>>>(p_h, ea1_w1 + HH * HH, nullptr, p_asrc, HH, 0, nullptr, TILES);
    k_ea_gather<<<gW, TB, sga0>>>(eattr, ea1_w1 + 2 * HH * HH, ea1_b1,
                                  nullptr, nullptr, nullptr, 0);
    k_mm<<<HB, TB, smm128>>>(p_acc, ea1_w2, nullptr, p_h, HH, MM_RELU | MM_BIASDEG, ea1_b2, TILES);

    // ---- TAG1 ----
    k_mm<<<HB, TB, smm128>>>(p_h, tag1_w, nullptr, p_out, HH, 0, nullptr, TILES);
    k_prop<<<gW, TB>>>(p_h, p_t1);
    k_mm<<<HB, TB, smm128>>>(p_t1, tag1_w + 1 * HH * HH, p_out, p_out, HH, MM_ACC, nullptr, TILES);
    k_prop<<<gW, TB>>>(p_t1, p_t2);
    k_mm<<<HB, TB, smm128>>>(p_t2, tag1_w + 2 * HH * HH, p_out, p_out, HH, MM_ACC, nullptr, TILES);
    k_prop<<<gW, TB>>>(p_t2, p_t1);
    k_mm<<<HB, TB, smm128>>>(p_t1, tag1_w + 3 * HH * HH, p_out, p_h, HH,
                             MM_ACC | MM_RELU | MM_BIAS, tag1_b, TILES);

    // ---- EA2 (F=128, OUT=16, no relu) -> d_out ----
    k_mm<<<HB, TB, smm128>>>(p_h, ea2_w1, nullptr, p_adst, HH, 0, nullptr, TILES);
    k_mm<<<HB, TB, smm128>>>(p_h, ea2_w1 + HH * HH, nullptr, p_asrc, HH, 0, nullptr, TILES);
    k_ea_gather<<<gW, TB, sga16>>>(eattr, ea2_w1 + 2 * HH * HH, ea2_b1,
                                   ea2_w2, ea2_b2, (float*)d_out, 16);
}

// round 4
// speedup vs baseline: 2.0861x; 1.0378x over previous
#include <cuda_runtime.h>

#define NN 20000
#define EE 160000
#define E2 320000
#define HH 128

#define MM_ACC 1
#define MM_RELU 2
#define MM_BIAS 4
#define MM_BIASDEG 8

typedef unsigned long long ull;

__device__ __forceinline__ ull pk2(float x) {
    ull r; asm("mov.b64 %0,{%1,%1};" : "=l"(r) : "f"(x)); return r;
}
__device__ __forceinline__ ull pkxy(float x, float y) {
    ull r; asm("mov.b64 %0,{%1,%2};" : "=l"(r) : "f"(x), "f"(y)); return r;
}
__device__ __forceinline__ ull fma2(ull a, ull b, ull c) {
    ull d; asm("fma.rn.f32x2 %0,%1,%2,%3;" : "=l"(d) : "l"(a), "l"(b), "l"(c)); return d;
}
__device__ __forceinline__ ull add2(ull a, ull b) {
    ull d; asm("add.rn.f32x2 %0,%1,%2;" : "=l"(d) : "l"(a), "l"(b)); return d;
}
__device__ __forceinline__ void upk(ull v, float& x, float& y) {
    asm("mov.b64 {%0,%1},%2;" : "=f"(x), "=f"(y) : "l"(v));
}

// ---------------- scratch ----------------
__device__ float g_h[NN * HH];
__device__ float g_adst[NN * HH];
__device__ float g_asrc[NN * HH];
__device__ float g_acc[NN * HH];
__device__ float g_t1[NN * HH];
__device__ float g_t2[NN * HH];
__device__ float g_out[NN * HH];
__device__ float g_dis[NN];
__device__ float g_degf[NN];
__device__ int g_rowptr[NN + 1];
__device__ int g_cursor[NN];
__device__ int g_blocksum[32];
__device__ int g_csr_src[E2];
__device__ int g_csr_ea[E2];

// ---------------- CSR build ----------------
__global__ void k_zero_int(int* p, int n) {
    int i = blockIdx.x * blockDim.x + threadIdx.x;
    if (i < n) p[i] = 0;
}

__global__ void k_count(const int* __restrict__ ei) {
    int e = blockIdx.x * blockDim.x + threadIdx.x;
    if (e >= E2) return;
    int d = (e < EE) ? ei[e + EE] : ei[e - EE];
    atomicAdd(&g_cursor[d], 1);
}

// phase A: 20 blocks x 1000 elements; per-block exclusive scan; zero cursor
__global__ void k_scanA() {
    __shared__ int s[1024];
    int tid = threadIdx.x;
    int base = blockIdx.x * 1000;
    int i = base + tid;
    int v = (tid < 1000 && i < NN) ? g_cursor[i] : 0;
    if (tid < 1000 && i < NN) g_cursor[i] = 0;
    s[tid] = v;
    __syncthreads();
    for (int off = 1; off < 1024; off <<= 1) {
        int t = (tid >= off) ? s[tid - off] : 0;
        __syncthreads();
        s[tid] += t;
        __syncthreads();
    }
    if (tid < 1000 && i < NN) g_rowptr[i] = s[tid] - v;
    if (tid == 1023) g_blocksum[blockIdx.x] = s[1023];
}

// phase B: single block: scan 20 block sums, add offsets, set rowptr[NN]
__global__ void k_scanB() {
    __shared__ int offs[21];
    int tid = threadIdx.x;
    if (tid == 0) {
        int run = 0;
        for (int b = 0; b < 20; b++) { offs[b] = run; run += g_blocksum[b]; }
        offs[20] = run;
        g_rowptr[NN] = run;
    }
    __syncthreads();
    for (int i = tid; i < NN; i += blockDim.x)
        g_rowptr[i] += offs[i / 1000];
}

__global__ void k_fill(const int* __restrict__ ei) {
    int e = blockIdx.x * blockDim.x + threadIdx.x;
    if (e >= E2) return;
    int srow, d, er;
    if (e < EE) { srow = ei[e]; d = ei[e + EE]; er = e; }
    else        { srow = ei[e]; d = ei[e - EE]; er = e - EE; }
    int idx = g_rowptr[d] + atomicAdd(&g_cursor[d], 1);
    g_csr_src[idx] = srow;
    g_csr_ea[idx] = er;
}

__global__ void k_dis() {
    int v = blockIdx.x * blockDim.x + threadIdx.x;
    if (v >= NN) return;
    int deg = g_rowptr[v + 1] - g_rowptr[v];
    float df = (float)deg;
    g_degf[v] = df;
    g_dis[v] = deg > 0 ? rsqrtf(df) : 0.f;
}

// ---------------- mask MLP + residual ----------------
__global__ void k_maskmlp(const float* __restrict__ x, const float* __restrict__ mask,
                          const float* __restrict__ w1, const float* __restrict__ b1,
                          const float* __restrict__ w2, const float* __restrict__ b2,
                          float* __restrict__ hout) {
    __shared__ float sw1[16 * HH], sb1[HH], sw2[HH * 16], sb2[16];
    for (int i = threadIdx.x; i < 16 * HH; i += blockDim.x) { sw1[i] = w1[i]; sw2[i] = w2[i]; }
    for (int i = threadIdx.x; i < HH; i += blockDim.x) sb1[i] = b1[i];
    if (threadIdx.x < 16) sb2[threadIdx.x] = b2[threadIdx.x];
    __syncthreads();
    int v = blockIdx.x * blockDim.x + threadIdx.x;
    if (v >= NN) return;
    float m[16], out[16];
#pragma unroll
    for (int i = 0; i < 16; i++) m[i] = mask[v * 16 + i];
#pragma unroll
    for (int o = 0; o < 16; o++) out[o] = sb2[o];
#pragma unroll 4
    for (int j = 0; j < HH; j++) {
        float a = sb1[j];
#pragma unroll
        for (int i = 0; i < 16; i++) a = fmaf(m[i], sw1[i * HH + j], a);
        a = fmaxf(a, 0.f);
#pragma unroll
        for (int o = 0; o < 16; o++) out[o] = fmaf(a, sw2[j * 16 + o], out[o]);
    }
#pragma unroll
    for (int o = 0; o < 16; o++) hout[v * 16 + o] = out[o] + x[v * 16 + o];
}

// ---------------- shared tile-MM core (operates from smem A-tile) ----------------
__device__ __forceinline__ void mm_tile(const float* __restrict__ sw, const float* __restrict__ sh,
                                        const float* __restrict__ Cin, float* __restrict__ Cout,
                                        int F, int flags, const float* __restrict__ bias,
                                        int vbase, int w, int lane) {
    ull acc[4][2];
#pragma unroll
    for (int i = 0; i < 4; i++) { acc[i][0] = 0ull; acc[i][1] = 0ull; }
    const float* h0 = &sh[(w * 4 + 0) * F];
    const float* h1 = &sh[(w * 4 + 1) * F];
    const float* h2 = &sh[(w * 4 + 2) * F];
    const float* h3 = &sh[(w * 4 + 3) * F];
    for (int j4 = 0; j4 < F; j4 += 4) {
        float4 hv0 = *(const float4*)&h0[j4];
        float4 hv1 = *(const float4*)&h1[j4];
        float4 hv2 = *(const float4*)&h2[j4];
        float4 hv3 = *(const float4*)&h3[j4];
#pragma unroll
        for (int jj = 0; jj < 4; jj++) {
            ulonglong2 wv = *(const ulonglong2*)&sw[(j4 + jj) * HH + lane * 4];
            float f0 = jj == 0 ? hv0.x : jj == 1 ? hv0.y : jj == 2 ? hv0.z : hv0.w;
            float f1 = jj == 0 ? hv1.x : jj == 1 ? hv1.y : jj == 2 ? hv1.z : hv1.w;
            float f2 = jj == 0 ? hv2.x : jj == 1 ? hv2.y : jj == 2 ? hv2.z : hv2.w;
            float f3 = jj == 0 ? hv3.x : jj == 1 ? hv3.y : jj == 2 ? hv3.z : hv3.w;
            ull a0 = pk2(f0), a1 = pk2(f1), a2 = pk2(f2), a3 = pk2(f3);
            acc[0][0] = fma2(a0, wv.x, acc[0][0]); acc[0][1] = fma2(a0, wv.y, acc[0][1]);
            acc[1][0] = fma2(a1, wv.x, acc[1][0]); acc[1][1] = fma2(a1, wv.y, acc[1][1]);
            acc[2][0] = fma2(a2, wv.x, acc[2][0]); acc[2][1] = fma2(a2, wv.y, acc[2][1]);
            acc[3][0] = fma2(a3, wv.x, acc[3][0]); acc[3][1] = fma2(a3, wv.y, acc[3][1]);
        }
    }
    int o = lane * 4;
#pragma unroll
    for (int i = 0; i < 4; i++) {
        int v = vbase + w * 4 + i;
        float4 r;
        upk(acc[i][0], r.x, r.y);
        upk(acc[i][1], r.z, r.w);
        if (flags & MM_BIAS) {
            r.x += bias[o]; r.y += bias[o + 1]; r.z += bias[o + 2]; r.w += bias[o + 3];
        }
        if (flags & MM_BIASDEG) {
            float dg = g_degf[v];
            r.x += dg * bias[o]; r.y += dg * bias[o + 1];
            r.z += dg * bias[o + 2]; r.w += dg * bias[o + 3];
        }
        if (flags & MM_ACC) {
            float4 c = *(const float4*)&Cin[v * HH + o];
            r.x += c.x; r.y += c.y; r.z += c.z; r.w += c.w;
        }
        if (flags & MM_RELU) {
            r.x = fmaxf(r.x, 0.f); r.y = fmaxf(r.y, 0.f);
            r.z = fmaxf(r.z, 0.f); r.w = fmaxf(r.w, 0.f);
        }
        *(float4*)&Cout[v * HH + o] = r;
    }
}

// ---------------- plain tiled matmul (persistent) ----------------
__global__ void k_mm(const float* __restrict__ A, const float* __restrict__ W,
                     const float* __restrict__ Cin, float* __restrict__ Cout,
                     int F, int flags, const float* __restrict__ bias, int ntiles) {
    extern __shared__ float sm[];
    float* sw = sm;
    float* sh = sm + F * HH;
    int tid = threadIdx.x;
    for (int i = tid * 4; i < F * HH; i += blockDim.x * 4)
        *(float4*)&sw[i] = *(const float4*)&W[i];
    int w = tid >> 5, lane = tid & 31;
    for (int tile = blockIdx.x; tile < ntiles; tile += gridDim.x) {
        int vbase = tile * 32;
        __syncthreads();
        for (int i = tid * 4; i < 32 * F; i += blockDim.x * 4)
            *(float4*)&sh[i] = *(const float4*)&A[vbase * F + i];
        __syncthreads();
        mm_tile(sw, sh, Cin, Cout, F, flags, bias, vbase, w, lane);
    }
}

// ---------------- dual matmul: blockIdx.y picks half (adst / asrc) ----------------
__global__ void k_mm2(const float* __restrict__ A, const float* __restrict__ Wbase,
                      float* __restrict__ C0, float* __restrict__ C1,
                      int F, int ntiles) {
    extern __shared__ float sm[];
    float* sw = sm;
    float* sh = sm + F * HH;
    int tid = threadIdx.x;
    const float* W = Wbase + blockIdx.y * F * HH;
    float* Cout = blockIdx.y ? C1 : C0;
    for (int i = tid * 4; i < F * HH; i += blockDim.x * 4)
        *(float4*)&sw[i] = *(const float4*)&W[i];
    int w = tid >> 5, lane = tid & 31;
    for (int tile = blockIdx.x; tile < ntiles; tile += gridDim.x) {
        int vbase = tile * 32;
        __syncthreads();
        for (int i = tid * 4; i < 32 * F; i += blockDim.x * 4)
            *(float4*)&sh[i] = *(const float4*)&A[vbase * F + i];
        __syncthreads();
        mm_tile(sw, sh, nullptr, Cout, F, 0, nullptr, vbase, w, lane);
    }
}

// ---------------- fused prop + matmul ----------------
// per tile: st[i] = dis[v]*sum_nbr dis[s]*tin[s]  (warp w handles nodes w*4..w*4+3)
// optionally write st to tout; then Cout = op(Cin + st@W)
__global__ void k_propmm(const float* __restrict__ tin, float* __restrict__ tout,
                         const float* __restrict__ W,
                         const float* __restrict__ Cin, float* __restrict__ Cout,
                         int flags, const float* __restrict__ bias,
                         int ntiles, int write_t) {
    extern __shared__ float sm[];
    float* sw = sm;              // 128*128
    float* st = sm + HH * HH;    // 32*128
    int tid = threadIdx.x;
    for (int i = tid * 4; i < HH * HH; i += blockDim.x * 4)
        *(float4*)&sw[i] = *(const float4*)&W[i];
    int w = tid >> 5, lane = tid & 31;
    int jo = lane * 4;
    for (int tile = blockIdx.x; tile < ntiles; tile += gridDim.x) {
        int vbase = tile * 32;
        __syncthreads();
#pragma unroll
        for (int i = 0; i < 4; i++) {
            int d = vbase + w * 4 + i;
            int beg = g_rowptr[d], end = g_rowptr[d + 1];
            float a0 = 0.f, a1 = 0.f, a2 = 0.f, a3 = 0.f;
            for (int idx = beg; idx < end; idx++) {
                int s = g_csr_src[idx];
                float ds = g_dis[s];
                float4 t = *(const float4*)&tin[s * HH + jo];
                a0 = fmaf(ds, t.x, a0); a1 = fmaf(ds, t.y, a1);
                a2 = fmaf(ds, t.z, a2); a3 = fmaf(ds, t.w, a3);
            }
            float dd = g_dis[d];
            float4 r = make_float4(dd * a0, dd * a1, dd * a2, dd * a3);
            *(float4*)&st[(w * 4 + i) * HH + jo] = r;
            if (write_t) *(float4*)&tout[d * HH + jo] = r;
        }
        __syncthreads();
        mm_tile(sw, st, Cin, Cout, HH, flags, bias, vbase, w, lane);
    }
}

// ---------------- EA edge gather (warp per dst node, f32x2 packed) ----------------
__global__ void k_ea_gather(const float* __restrict__ eattr,
                            const float* __restrict__ w1ea, const float* __restrict__ b1,
                            const float* __restrict__ w2, const float* __restrict__ b2,
                            float* __restrict__ out, int Ofin) {
    extern __shared__ float sm[];
    float* sw1 = sm;             // 16*128
    float* sb1 = sm + 16 * HH;   // 128
    float* sw2t = sb1 + HH;      // Ofin*128 (transposed)
    float* sb2 = sw2t + HH * Ofin;
    float* buf = sb2 + Ofin;     // 8*128 when Ofin
    int tid = threadIdx.x;
    for (int i = tid; i < 16 * HH; i += blockDim.x) sw1[i] = w1ea[i];
    for (int i = tid; i < HH; i += blockDim.x) sb1[i] = b1[i];
    if (Ofin) {
        for (int i = tid; i < HH * Ofin; i += blockDim.x) {
            int j = i >> 4, o = i & 15;
            sw2t[o * HH + j] = w2[i];
        }
        if (tid < Ofin) sb2[tid] = b2[tid];
    }
    __syncthreads();

    int w = tid >> 5, lane = tid & 31;
    int jo = lane * 4;
    for (int d = blockIdx.x * 8 + w; d < NN; d += gridDim.x * 8) {
        int beg = g_rowptr[d], end = g_rowptr[d + 1];
        float4 ad = *(const float4*)&g_adst[d * HH + jo];
        ull zb0 = pkxy(ad.x + sb1[jo], ad.y + sb1[jo + 1]);
        ull zb1 = pkxy(ad.z + sb1[jo + 2], ad.w + sb1[jo + 3]);
        float a0 = 0.f, a1 = 0.f, a2 = 0.f, a3 = 0.f;
        for (int idx = beg; idx < end; idx++) {
            int s = g_csr_src[idx];
            int er = g_csr_ea[idx];
            float eav = (lane < 16) ? eattr[er * 16 + lane] : 0.f;
            ulonglong2 as = *(const ulonglong2*)&g_asrc[s * HH + jo];
            ull z0 = add2(zb0, as.x);
            ull z1 = add2(zb1, as.y);
#pragma unroll
            for (int i = 0; i < 16; i++) {
                float a = __shfl_sync(0xffffffffu, eav, i);
                ull ap = pk2(a);
                ulonglong2 wv = *(const ulonglong2*)&sw1[i * HH + jo];
                z0 = fma2(ap, wv.x, z0);
                z1 = fma2(ap, wv.y, z1);
            }
            float f0, f1, f2, f3;
            upk(z0, f0, f1);
            upk(z1, f2, f3);
            a0 += fmaxf(f0, 0.f); a1 += fmaxf(f1, 0.f);
            a2 += fmaxf(f2, 0.f); a3 += fmaxf(f3, 0.f);
        }
        if (!Ofin) {
            *(float4*)&g_acc[d * HH + jo] = make_float4(a0, a1, a2, a3);
        } else {
            *(float4*)&buf[w * HH + jo] = make_float4(a0, a1, a2, a3);
            __syncwarp();
            if (lane < 16) {
                int o = lane;
                float acc = g_degf[d] * sb2[o];
                for (int j4 = 0; j4 < HH; j4 += 4) {
                    float4 b = *(const float4*)&buf[w * HH + j4];
                    float4 wv = *(const float4*)&sw2t[o * HH + j4];
                    acc = fmaf(b.x, wv.x, acc); acc = fmaf(b.y, wv.y, acc);
                    acc = fmaf(b.z, wv.z, acc); acc = fmaf(b.w, wv.w, acc);
                }
                out[d * 16 + o] = acc;
            }
            __syncwarp();
        }
    }
}

// ---------------- host ----------------
extern "C" void kernel_launch(void* const* d_in, const int* in_sizes, int n_in,
                              void* d_out, int out_size) {
    int eidx, wb;
    if (in_sizes[3] == 2 * EE) { eidx = 3; wb = 4; }
    else                       { eidx = n_in - 1; wb = 3; }

    const float* x     = (const float*)d_in[0];
    const float* mask  = (const float*)d_in[1];
    const float* eattr = (const float*)d_in[2];
    const int*   ei    = (const int*)d_in[eidx];
    const float* m_w1   = (const float*)d_in[wb + 0];
    const float* m_b1   = (const float*)d_in[wb + 1];
    const float* m_w2   = (const float*)d_in[wb + 2];
    const float* m_b2   = (const float*)d_in[wb + 3];
    const float* ea0_w1 = (const float*)d_in[wb + 4];
    const float* ea0_b1 = (const float*)d_in[wb + 5];
    const float* ea0_w2 = (const float*)d_in[wb + 6];
    const float* ea0_b2 = (const float*)d_in[wb + 7];
    const float* tag0_w = (const float*)d_in[wb + 8];
    const float* tag0_b = (const float*)d_in[wb + 9];
    const float* ea1_w1 = (const float*)d_in[wb + 10];
    const float* ea1_b1 = (const float*)d_in[wb + 11];
    const float* ea1_w2 = (const float*)d_in[wb + 12];
    const float* ea1_b2 = (const float*)d_in[wb + 13];
    const float* tag1_w = (const float*)d_in[wb + 14];
    const float* tag1_b = (const float*)d_in[wb + 15];
    const float* ea2_w1 = (const float*)d_in[wb + 16];
    const float* ea2_b1 = (const float*)d_in[wb + 17];
    const float* ea2_w2 = (const float*)d_in[wb + 18];
    const float* ea2_b2 = (const float*)d_in[wb + 19];

    float *p_h, *p_adst, *p_asrc, *p_acc, *p_t1, *p_t2, *p_out;
    int* p_cur;
    cudaGetSymbolAddress((void**)&p_h, g_h);
    cudaGetSymbolAddress((void**)&p_adst, g_adst);
    cudaGetSymbolAddress((void**)&p_asrc, g_asrc);
    cudaGetSymbolAddress((void**)&p_acc, g_acc);
    cudaGetSymbolAddress((void**)&p_t1, g_t1);
    cudaGetSymbolAddress((void**)&p_t2, g_t2);
    cudaGetSymbolAddress((void**)&p_out, g_out);
    cudaGetSymbolAddress((void**)&p_cur, g_cursor);

    static bool attr_done = false;
    if (!attr_done) {
        cudaFuncSetAttribute(k_mm, cudaFuncAttributeMaxDynamicSharedMemorySize, 84 * 1024);
        cudaFuncSetAttribute(k_mm2, cudaFuncAttributeMaxDynamicSharedMemorySize, 84 * 1024);
        cudaFuncSetAttribute(k_propmm, cudaFuncAttributeMaxDynamicSharedMemorySize, 84 * 1024);
        cudaFuncSetAttribute(k_ea_gather, cudaFuncAttributeMaxDynamicSharedMemorySize, 48 * 1024);
        attr_done = true;
    }

    const int TB = 256;
    const int gN = (NN + TB - 1) / TB;
    const int gE = (E2 + TB - 1) / TB;
    const int TILES = NN / 32;   // 625
    const int HB = 296;          // persistent blocks (2/SM)
    const int gW = 2500;
    const size_t smm128 = (size_t)(HH * HH + 32 * HH) * 4;   // 80KB
    const size_t smm16  = (size_t)(16 * HH + 32 * 16) * 4;
    const size_t sga0   = (size_t)(16 * HH + HH) * 4;
    const size_t sga16  = (size_t)(16 * HH + HH + HH * 16 + 16 + 8 * HH) * 4;

    // CSR
    k_zero_int<<<gN, TB>>>(p_cur, NN);
    k_count<<<gE, TB>>>(ei);
    k_scanA<<<20, 1024>>>();
    k_scanB<<<1, 1024>>>();
    k_fill<<<gE, TB>>>(ei);
    k_dis<<<gN, TB>>>();

    // mask MLP + residual -> g_h [N,16]
    k_maskmlp<<<gN, TB>>>(x, mask, m_w1, m_b1, m_w2, m_b2, p_h);

    // ---- EA0 (F=16) ----
    k_mm2<<<dim3(TILES, 2), TB, smm16>>>(p_h, ea0_w1, p_adst, p_asrc, 16, TILES);
    k_ea_gather<<<gW, TB, sga0>>>(eattr, ea0_w1 + 2 * 16 * HH, ea0_b1,
                                  nullptr, nullptr, nullptr, 0);
    k_mm<<<HB, TB, smm128>>>(p_acc, ea0_w2, nullptr, p_h, HH, MM_RELU | MM_BIASDEG, ea0_b2, TILES);

    // ---- TAG0 (4 launches) ----
    k_mm<<<HB, TB, smm128>>>(p_h, tag0_w, nullptr, p_out, HH, 0, nullptr, TILES);
    k_propmm<<<HB, TB, smm128>>>(p_h, p_t1, tag0_w + 1 * HH * HH, p_out, p_out,
                                 MM_ACC, nullptr, TILES, 1);
    k_propmm<<<HB, TB, smm128>>>(p_t1, p_t2, tag0_w + 2 * HH * HH, p_out, p_out,
                                 MM_ACC, nullptr, TILES, 1);
    k_propmm<<<HB, TB, smm128>>>(p_t2, nullptr, tag0_w + 3 * HH * HH, p_out, p_h,
                                 MM_ACC | MM_RELU | MM_BIAS, tag0_b, TILES, 0);

    // ---- EA1 (F=128) ----
    k_mm2<<<dim3(HB, 2), TB, smm128>>>(p_h, ea1_w1, p_adst, p_asrc, HH, TILES);
    k_ea_gather<<<gW, TB, sga0>>>(eattr, ea1_w1 + 2 * HH * HH, ea1_b1,
                                  nullptr, nullptr, nullptr, 0);
    k_mm<<<HB, TB, smm128>>>(p_acc, ea1_w2, nullptr, p_h, HH, MM_RELU | MM_BIASDEG, ea1_b2, TILES);

    // ---- TAG1 ----
    k_mm<<<HB, TB, smm128>>>(p_h, tag1_w, nullptr, p_out, HH, 0, nullptr, TILES);
    k_propmm<<<HB, TB, smm128>>>(p_h, p_t1, tag1_w + 1 * HH * HH, p_out, p_out,
                                 MM_ACC, nullptr, TILES, 1);
    k_propmm<<<HB, TB, smm128>>>(p_t1, p_t2, tag1_w + 2 * HH * HH, p_out, p_out,
                                 MM_ACC, nullptr, TILES, 1);
    k_propmm<<<HB, TB, smm128>>>(p_t2, nullptr, tag1_w + 3 * HH * HH, p_out, p_h,
                                 MM_ACC | MM_RELU | MM_BIAS, tag1_b, TILES, 0);

    // ---- EA2 (F=128, OUT=16, no relu) -> d_out ----
    k_mm2<<<dim3(HB, 2), TB, smm128>>>(p_h, ea2_w1, p_adst, p_asrc, HH, TILES);
    k_ea_gather<<<gW, TB, sga16>>>(eattr, ea2_w1 + 2 * HH * HH, ea2_b1,
                                   ea2_w2, ea2_b2, (float*)d_out, 16);
}